// round 4
// baseline (speedup 1.0000x reference)
#include <cuda_runtime.h>
#include <math.h>

#define D_MODEL 1024
#define N_HEADS 16
#define D_HEAD  64
#define SEQ     2048
#define BATCH   2
#define MTOT    (BATCH*SEQ)      /* 4096 */
#define QKV_N   (3*D_MODEL)      /* 3072 */

// Scratch (device globals; no allocations allowed)
__device__ float g_qkv[(size_t)MTOT*QKV_N];   // [M][3072]: q|k|v per row
__device__ float g_ctx[(size_t)MTOT*D_MODEL]; // [M][1024]: attention output

// ---------------------------------------------------------------------------
// GEMM: C[m][n] = sum_k A[m][k]*B[n][k] + bias[n]   (both operands K-major)
// 128x128 block tile, BK=16, 256 threads, 8x8 register micro-tile.
// ---------------------------------------------------------------------------
__global__ void __launch_bounds__(256, 2) sgemm_nt_bias(
    const float* __restrict__ A, const float* __restrict__ B,
    const float* __restrict__ bias, float* __restrict__ C,
    int M, int N, int K)
{
    __shared__ float As[16][132];
    __shared__ float Bs[16][132];

    const int bm = blockIdx.y * 128;
    const int bn = blockIdx.x * 128;
    const int tid = threadIdx.x;
    const int tx = tid & 15, ty = tid >> 4;

    float acc[8][8];
#pragma unroll
    for (int i = 0; i < 8; i++)
#pragma unroll
        for (int j = 0; j < 8; j++) acc[i][j] = 0.f;

    const float* Ab = A + (size_t)bm * K;
    const float* Bb = B + (size_t)bn * K;

    for (int k0 = 0; k0 < K; k0 += 16) {
#pragma unroll
        for (int l = 0; l < 2; l++) {
            int f   = tid + l * 256;       // float4 id: 512 total
            int row = f >> 2;              // 0..127
            int c4  = (f & 3) * 4;         // 0,4,8,12
            float4 av = *(const float4*)(Ab + (size_t)row * K + k0 + c4);
            As[c4+0][row] = av.x; As[c4+1][row] = av.y;
            As[c4+2][row] = av.z; As[c4+3][row] = av.w;
            float4 bv = *(const float4*)(Bb + (size_t)row * K + k0 + c4);
            Bs[c4+0][row] = bv.x; Bs[c4+1][row] = bv.y;
            Bs[c4+2][row] = bv.z; Bs[c4+3][row] = bv.w;
        }
        __syncthreads();
#pragma unroll
        for (int k = 0; k < 16; k++) {
            float a[8], b[8];
            *(float4*)(a)     = *(const float4*)&As[k][ty*8];
            *(float4*)(a + 4) = *(const float4*)&As[k][ty*8 + 4];
            *(float4*)(b)     = *(const float4*)&Bs[k][tx*8];
            *(float4*)(b + 4) = *(const float4*)&Bs[k][tx*8 + 4];
#pragma unroll
            for (int i = 0; i < 8; i++)
#pragma unroll
                for (int j = 0; j < 8; j++)
                    acc[i][j] = fmaf(a[i], b[j], acc[i][j]);
        }
        __syncthreads();
    }

#pragma unroll
    for (int i = 0; i < 8; i++) {
        int row = bm + ty*8 + i;
#pragma unroll
        for (int j4 = 0; j4 < 2; j4++) {
            int col = bn + tx*8 + j4*4;
            float4 o;
            o.x = acc[i][j4*4+0] + bias[col+0];
            o.y = acc[i][j4*4+1] + bias[col+1];
            o.z = acc[i][j4*4+2] + bias[col+2];
            o.w = acc[i][j4*4+3] + bias[col+3];
            *(float4*)(C + (size_t)row * N + col) = o;
        }
    }
}

// ---------------------------------------------------------------------------
// RoPE in-place on q and k halves of g_qkv. One thread per (m, h, i<32) pair.
// ---------------------------------------------------------------------------
__global__ void rope_kernel(float* __restrict__ qkv)
{
    int idx = blockIdx.x * 256 + threadIdx.x;   // exactly MTOT*16*32 threads
    int i = idx & 31;
    int h = (idx >> 5) & (N_HEADS - 1);
    int m = idx >> 9;
    int s = m & (SEQ - 1);

    float inv = powf(10000.0f, -(2.0f * (float)i) / 64.0f);
    float ang = (float)s * inv;
    float sn, cs;
    sincosf(ang, &sn, &cs);

    float* p = qkv + (size_t)m * QKV_N + h * 64;   // q
#pragma unroll
    for (int part = 0; part < 2; part++) {
        float x1 = p[i], x2 = p[i + 32];
        p[i]      = x1 * cs - x2 * sn;
        p[i + 32] = x2 * cs + x1 * sn;
        p += D_MODEL;                              // then k
    }
}

// ---------------------------------------------------------------------------
// Flash attention, causal. One block per (q-tile 64, head, batch).
// 256 threads = 16x16; each thread owns a 4x4 tile of S and of O.
// Smem: Qs (d-major), KP (K d-major, then re-used for P j-major), Vs (j-major).
// ---------------------------------------------------------------------------
__global__ void __launch_bounds__(256) attn_kernel(
    const float* __restrict__ qkv, float* __restrict__ ctx)
{
    __shared__ float Qs[64*64];
    __shared__ float KP[64*64];
    __shared__ float Vs[64*64];

    const int qt = blockIdx.x, h = blockIdx.y, b = blockIdx.z;
    const int tid = threadIdx.x;
    const int tx = tid & 15, ty = tid >> 4;
    const int qBase = qt * 64;
    const float* base = qkv + (size_t)b * SEQ * QKV_N + h * 64;

    // Load Q tile transposed: Qs[d][row]
#pragma unroll
    for (int l = 0; l < 4; l++) {
        int f   = tid + l * 256;       // 1024 float4s
        int row = f >> 4;              // 0..63
        int d4  = (f & 15) * 4;
        float4 v = *(const float4*)(base + (size_t)(qBase + row) * QKV_N + d4);
        Qs[(d4+0)*64 + row] = v.x; Qs[(d4+1)*64 + row] = v.y;
        Qs[(d4+2)*64 + row] = v.z; Qs[(d4+3)*64 + row] = v.w;
    }

    float m_i[4], l_i[4], acc[4][4];
#pragma unroll
    for (int r = 0; r < 4; r++) {
        m_i[r] = -1e30f; l_i[r] = 0.f;
#pragma unroll
        for (int c = 0; c < 4; c++) acc[r][c] = 0.f;
    }

    for (int kt = 0; kt <= qt; kt++) {
        const int kBase = kt * 64;
        __syncthreads();   // previous iter done reading KP/Vs

        // Load K transposed into KP, V natural into Vs
#pragma unroll
        for (int l = 0; l < 4; l++) {
            int f   = tid + l * 256;
            int row = f >> 4;
            int d4  = (f & 15) * 4;
            const float* kp = base + (size_t)(kBase + row) * QKV_N + D_MODEL + d4;
            float4 kv = *(const float4*)kp;
            KP[(d4+0)*64 + row] = kv.x; KP[(d4+1)*64 + row] = kv.y;
            KP[(d4+2)*64 + row] = kv.z; KP[(d4+3)*64 + row] = kv.w;
            float4 vv = *(const float4*)(kp + D_MODEL);
            *(float4*)&Vs[row*64 + d4] = vv;
        }
        __syncthreads();

        // S = Q K^T (outer product over d)
        float s[4][4];
#pragma unroll
        for (int r = 0; r < 4; r++)
#pragma unroll
            for (int c = 0; c < 4; c++) s[r][c] = 0.f;
#pragma unroll
        for (int d = 0; d < 64; d++) {
            float4 a  = *(const float4*)&Qs[d*64 + ty*4];
            float4 bb = *(const float4*)&KP[d*64 + tx*4];
            float av[4] = {a.x, a.y, a.z, a.w};
            float bv[4] = {bb.x, bb.y, bb.z, bb.w};
#pragma unroll
            for (int r = 0; r < 4; r++)
#pragma unroll
                for (int c = 0; c < 4; c++)
                    s[r][c] = fmaf(av[r], bv[c], s[r][c]);
        }
#pragma unroll
        for (int r = 0; r < 4; r++)
#pragma unroll
            for (int c = 0; c < 4; c++) s[r][c] *= 0.125f;

        if (kt == qt) {   // diagonal tile: causal mask
#pragma unroll
            for (int r = 0; r < 4; r++)
#pragma unroll
                for (int c = 0; c < 4; c++)
                    if (tx*4 + c > ty*4 + r) s[r][c] = -1e30f;
        }

        // Online softmax update (row stats replicated across the 16 tx lanes)
#pragma unroll
        for (int r = 0; r < 4; r++) {
            float mt = fmaxf(fmaxf(s[r][0], s[r][1]), fmaxf(s[r][2], s[r][3]));
#pragma unroll
            for (int off = 1; off < 16; off <<= 1)
                mt = fmaxf(mt, __shfl_xor_sync(0xffffffffu, mt, off));
            float mnew  = fmaxf(m_i[r], mt);
            float alpha = __expf(m_i[r] - mnew);
            float sum = 0.f;
#pragma unroll
            for (int c = 0; c < 4; c++) {
                s[r][c] = __expf(s[r][c] - mnew);
                sum += s[r][c];
            }
#pragma unroll
            for (int off = 1; off < 16; off <<= 1)
                sum += __shfl_xor_sync(0xffffffffu, sum, off);
            l_i[r] = l_i[r] * alpha + sum;
            m_i[r] = mnew;
#pragma unroll
            for (int c = 0; c < 4; c++) acc[r][c] *= alpha;
        }

        __syncthreads();   // all done reading KP as K-scores
        // Stage P transposed (j-major) into KP
#pragma unroll
        for (int r = 0; r < 4; r++)
#pragma unroll
            for (int c = 0; c < 4; c++)
                KP[(tx*4 + c)*64 + ty*4 + r] = s[r][c];
        __syncthreads();

        // O += P V (outer product over j)
#pragma unroll
        for (int j = 0; j < 64; j++) {
            float4 a  = *(const float4*)&KP[j*64 + ty*4];
            float4 bb = *(const float4*)&Vs[j*64 + tx*4];
            float av[4] = {a.x, a.y, a.z, a.w};
            float bv[4] = {bb.x, bb.y, bb.z, bb.w};
#pragma unroll
            for (int r = 0; r < 4; r++)
#pragma unroll
                for (int c = 0; c < 4; c++)
                    acc[r][c] = fmaf(av[r], bv[c], acc[r][c]);
        }
    }

    // Epilogue: normalize and write ctx [M][1024]
    float* out = ctx + (size_t)(b * SEQ + qBase) * D_MODEL + h * 64;
#pragma unroll
    for (int r = 0; r < 4; r++) {
        float inv = 1.f / l_i[r];
        float4 o;
        o.x = acc[r][0] * inv; o.y = acc[r][1] * inv;
        o.z = acc[r][2] * inv; o.w = acc[r][3] * inv;
        *(float4*)(out + (size_t)(ty*4 + r) * D_MODEL + tx*4) = o;
    }
}

// ---------------------------------------------------------------------------
extern "C" void kernel_launch(void* const* d_in, const int* in_sizes, int n_in,
                              void* d_out, int out_size)
{
    const float* x      = (const float*)d_in[0];
    const float* qkv_w  = (const float*)d_in[1];
    const float* qkv_b  = (const float*)d_in[2];
    const float* proj_w = (const float*)d_in[3];
    const float* proj_b = (const float*)d_in[4];
    float* out = (float*)d_out;

    float *qkv, *ctx;
    cudaGetSymbolAddress((void**)&qkv, g_qkv);
    cudaGetSymbolAddress((void**)&ctx, g_ctx);

    // 1) QKV projection: [4096,1024] @ [3072,1024]^T + bias
    sgemm_nt_bias<<<dim3(QKV_N/128, MTOT/128), 256>>>(
        x, qkv_w, qkv_b, qkv, MTOT, QKV_N, D_MODEL);

    // 2) RoPE on q,k in-place
    rope_kernel<<<(MTOT * N_HEADS * 32) / 256, 256>>>(qkv);

    // 3) Causal flash attention -> ctx [M][1024]
    attn_kernel<<<dim3(SEQ/64, N_HEADS, BATCH), 256>>>(qkv, ctx);

    // 4) Output projection: ctx @ proj_w^T + bias -> out
    sgemm_nt_bias<<<dim3(D_MODEL/128, MTOT/128), 256>>>(
        ctx, proj_w, proj_b, out, MTOT, D_MODEL, D_MODEL);
}

// round 5
// speedup vs baseline: 1.2256x; 1.2256x over previous
#include <cuda_runtime.h>
#include <math.h>

#define D_MODEL 1024
#define N_HEADS 16
#define D_HEAD  64
#define SEQ     2048
#define BATCH   2
#define MTOT    (BATCH*SEQ)      /* 4096 */
#define QKV_N   (3*D_MODEL)      /* 3072 */

// Scratch (device globals; no allocations allowed)
__device__ float g_qkv[(size_t)MTOT*QKV_N];    // [M][3072]: q|k|v per row
__device__ float g_qt[(size_t)BATCH*N_HEADS*D_HEAD*SEQ]; // [B][H][64][S] d-major, rope'd
__device__ float g_kt[(size_t)BATCH*N_HEADS*D_HEAD*SEQ]; // [B][H][64][S] d-major, rope'd
__device__ float g_ctx[(size_t)MTOT*D_MODEL];  // [M][1024]: attention output

// ---------------------------------------------------------------------------
// GEMM: C[m][n] = sum_k A[m][k]*B[n][k] + bias[n]  (unchanged from baseline)
// ---------------------------------------------------------------------------
__global__ void __launch_bounds__(256, 2) sgemm_nt_bias(
    const float* __restrict__ A, const float* __restrict__ B,
    const float* __restrict__ bias, float* __restrict__ C,
    int M, int N, int K)
{
    __shared__ float As[16][132];
    __shared__ float Bs[16][132];

    const int bm = blockIdx.y * 128;
    const int bn = blockIdx.x * 128;
    const int tid = threadIdx.x;
    const int tx = tid & 15, ty = tid >> 4;

    float acc[8][8];
#pragma unroll
    for (int i = 0; i < 8; i++)
#pragma unroll
        for (int j = 0; j < 8; j++) acc[i][j] = 0.f;

    const float* Ab = A + (size_t)bm * K;
    const float* Bb = B + (size_t)bn * K;

    for (int k0 = 0; k0 < K; k0 += 16) {
#pragma unroll
        for (int l = 0; l < 2; l++) {
            int f   = tid + l * 256;
            int row = f >> 2;
            int c4  = (f & 3) * 4;
            float4 av = *(const float4*)(Ab + (size_t)row * K + k0 + c4);
            As[c4+0][row] = av.x; As[c4+1][row] = av.y;
            As[c4+2][row] = av.z; As[c4+3][row] = av.w;
            float4 bv = *(const float4*)(Bb + (size_t)row * K + k0 + c4);
            Bs[c4+0][row] = bv.x; Bs[c4+1][row] = bv.y;
            Bs[c4+2][row] = bv.z; Bs[c4+3][row] = bv.w;
        }
        __syncthreads();
#pragma unroll
        for (int k = 0; k < 16; k++) {
            float a[8], b[8];
            *(float4*)(a)     = *(const float4*)&As[k][ty*8];
            *(float4*)(a + 4) = *(const float4*)&As[k][ty*8 + 4];
            *(float4*)(b)     = *(const float4*)&Bs[k][tx*8];
            *(float4*)(b + 4) = *(const float4*)&Bs[k][tx*8 + 4];
#pragma unroll
            for (int i = 0; i < 8; i++)
#pragma unroll
                for (int j = 0; j < 8; j++)
                    acc[i][j] = fmaf(a[i], b[j], acc[i][j]);
        }
        __syncthreads();
    }

#pragma unroll
    for (int i = 0; i < 8; i++) {
        int row = bm + ty*8 + i;
#pragma unroll
        for (int j4 = 0; j4 < 2; j4++) {
            int col = bn + tx*8 + j4*4;
            float4 o;
            o.x = acc[i][j4*4+0] + bias[col+0];
            o.y = acc[i][j4*4+1] + bias[col+1];
            o.z = acc[i][j4*4+2] + bias[col+2];
            o.w = acc[i][j4*4+3] + bias[col+3];
            *(float4*)(C + (size_t)row * N + col) = o;
        }
    }
}

// ---------------------------------------------------------------------------
// RoPE + transpose: read q,k from g_qkv, rotate, write d-major [B][H][64][S].
// Block = one (s-tile 64, head, batch). Smem staging, stride-65 (scalar access).
// ---------------------------------------------------------------------------
__global__ void __launch_bounds__(256) rope_transpose(
    const float* __restrict__ qkv, float* __restrict__ qt, float* __restrict__ kt)
{
    __shared__ float Tq[64*65];
    __shared__ float Tk[64*65];

    const int st = blockIdx.x, h = blockIdx.y, b = blockIdx.z;
    const int s0 = st * 64;
    const int tid = threadIdx.x;

    // Load 64 s-rows of q and k (coalesced), store scalars (stride 65)
#pragma unroll
    for (int l = 0; l < 4; l++) {
        int f = tid + l * 256;
        int srow = f >> 4;
        int d4 = (f & 15) * 4;
        const float* p = qkv + (size_t)(b * SEQ + s0 + srow) * QKV_N + h * 64 + d4;
        float4 qv = *(const float4*)p;
        float4 kv = *(const float4*)(p + D_MODEL);
        Tq[srow*65 + d4+0] = qv.x; Tq[srow*65 + d4+1] = qv.y;
        Tq[srow*65 + d4+2] = qv.z; Tq[srow*65 + d4+3] = qv.w;
        Tk[srow*65 + d4+0] = kv.x; Tk[srow*65 + d4+1] = kv.y;
        Tk[srow*65 + d4+2] = kv.z; Tk[srow*65 + d4+3] = kv.w;
    }
    __syncthreads();

    // Write transposed with RoPE applied: each thread writes 4 s at one d row
    const size_t obase = ((size_t)(b * N_HEADS + h)) * D_HEAD * SEQ;
#pragma unroll
    for (int l = 0; l < 4; l++) {
        int f = tid + l * 256;
        int d = f >> 4;
        int s4 = (f & 15) * 4;
        int i = d & 31;
        bool hi = d >= 32;
        float inv = powf(10000.0f, -(2.0f * (float)i) / 64.0f);
        float4 oq, ok;
        float* pq = (float*)&oq;
        float* pk = (float*)&ok;
#pragma unroll
        for (int u = 0; u < 4; u++) {
            int s = s4 + u;
            float ang = (float)(s0 + s) * inv;
            float sn, cs;
            sincosf(ang, &sn, &cs);
            float q1 = Tq[s*65 + d], q2 = Tq[s*65 + (d ^ 32)];
            float k1 = Tk[s*65 + d], k2 = Tk[s*65 + (d ^ 32)];
            pq[u] = hi ? (q1 * cs + q2 * sn) : (q1 * cs - q2 * sn);
            pk[u] = hi ? (k1 * cs + k2 * sn) : (k1 * cs - k2 * sn);
        }
        *(float4*)(qt + obase + (size_t)d * SEQ + s0 + s4) = oq;
        *(float4*)(kt + obase + (size_t)d * SEQ + s0 + s4) = ok;
    }
}

// ---------------------------------------------------------------------------
// Flash attention v3, causal. Block per (q-tile 64, head, batch), 256 thr.
// Q,K read d-major from g_qt/g_kt (conflict-free direct STS).
// K/V register-double-buffered (LDG kt+1 hidden under compute of kt).
// P stored row-major in the K smem region (clean float4 STS, broadcast LDS).
// ---------------------------------------------------------------------------
__global__ void __launch_bounds__(256, 2) attn_kernel(
    const float* __restrict__ qt, const float* __restrict__ ktb,
    const float* __restrict__ qkv, float* __restrict__ ctx)
{
    __shared__ float Qs[64*64];   // [d][s-local]
    __shared__ float KP[64*64];   // K: [d][s-local]; then P: [q-row][j] row-major
    __shared__ float Vs[64*64];   // [j][d]

    const int qtile = blockIdx.x, h = blockIdx.y, b = blockIdx.z;
    const int tid = threadIdx.x;
    const int tx = tid & 15, ty = tid >> 4;
    const int qBase = qtile * 64;

    const size_t hbase = ((size_t)(b * N_HEADS + h)) * D_HEAD * SEQ;
    const float* qtp = qt + hbase;
    const float* ktp = ktb + hbase;
    const float* vbase = qkv + (size_t)b * SEQ * QKV_N + 2 * D_MODEL + h * 64;

    // Load Q tile: direct d-major float4 STS (conflict-free)
#pragma unroll
    for (int l = 0; l < 4; l++) {
        int f = tid + l * 256;
        int d = f >> 4;
        int s4 = (f & 15) * 4;
        *(float4*)&Qs[d*64 + s4] =
            *(const float4*)(qtp + (size_t)d * SEQ + qBase + s4);
    }

    // Prologue: load K/V tile 0 into registers
    float4 kreg[4], vreg[4];
#pragma unroll
    for (int l = 0; l < 4; l++) {
        int f = tid + l * 256;
        int d = f >> 4;          // K: d-row   V: j-row
        int c4 = (f & 15) * 4;   // K: s-col   V: d-col
        kreg[l] = *(const float4*)(ktp + (size_t)d * SEQ + 0 + c4);
        vreg[l] = *(const float4*)(vbase + (size_t)(0 + d) * QKV_N + c4);
    }

    float m_i[4], l_i[4], acc[4][4];
#pragma unroll
    for (int r = 0; r < 4; r++) {
        m_i[r] = -1e30f; l_i[r] = 0.f;
#pragma unroll
        for (int c = 0; c < 4; c++) acc[r][c] = 0.f;
    }

    for (int kt = 0; kt <= qtile; kt++) {
        __syncthreads();   // (A) prior PV done reading KP(P)/Vs

        // STS K,V from registers (direct, conflict-free)
#pragma unroll
        for (int l = 0; l < 4; l++) {
            int f = tid + l * 256;
            int d = f >> 4;
            int c4 = (f & 15) * 4;
            *(float4*)&KP[d*64 + c4] = kreg[l];
            *(float4*)&Vs[d*64 + c4] = vreg[l];
        }
        __syncthreads();   // (B)

        // Prefetch next tile (latency hidden under S + softmax + PV)
        if (kt < qtile) {
            const int nBase = (kt + 1) * 64;
#pragma unroll
            for (int l = 0; l < 4; l++) {
                int f = tid + l * 256;
                int d = f >> 4;
                int c4 = (f & 15) * 4;
                kreg[l] = *(const float4*)(ktp + (size_t)d * SEQ + nBase + c4);
                vreg[l] = *(const float4*)(vbase + (size_t)(nBase + d) * QKV_N + c4);
            }
        }

        // S = Q K^T (outer product over d)
        float s[4][4];
#pragma unroll
        for (int r = 0; r < 4; r++)
#pragma unroll
            for (int c = 0; c < 4; c++) s[r][c] = 0.f;
#pragma unroll 16
        for (int d = 0; d < 64; d++) {
            float4 a  = *(const float4*)&Qs[d*64 + ty*4];
            float4 bb = *(const float4*)&KP[d*64 + tx*4];
            float av[4] = {a.x, a.y, a.z, a.w};
            float bv[4] = {bb.x, bb.y, bb.z, bb.w};
#pragma unroll
            for (int r = 0; r < 4; r++)
#pragma unroll
                for (int c = 0; c < 4; c++)
                    s[r][c] = fmaf(av[r], bv[c], s[r][c]);
        }
#pragma unroll
        for (int r = 0; r < 4; r++)
#pragma unroll
            for (int c = 0; c < 4; c++) s[r][c] *= 0.125f;

        if (kt == qtile) {   // diagonal tile: causal mask
#pragma unroll
            for (int r = 0; r < 4; r++)
#pragma unroll
                for (int c = 0; c < 4; c++)
                    if (tx*4 + c > ty*4 + r) s[r][c] = -1e30f;
        }

        // Online softmax (row stats replicated across the 16 tx lanes)
#pragma unroll
        for (int r = 0; r < 4; r++) {
            float mt = fmaxf(fmaxf(s[r][0], s[r][1]), fmaxf(s[r][2], s[r][3]));
#pragma unroll
            for (int off = 1; off < 16; off <<= 1)
                mt = fmaxf(mt, __shfl_xor_sync(0xffffffffu, mt, off));
            float mnew  = fmaxf(m_i[r], mt);
            float alpha = __expf(m_i[r] - mnew);
            float sum = 0.f;
#pragma unroll
            for (int c = 0; c < 4; c++) {
                s[r][c] = __expf(s[r][c] - mnew);
                sum += s[r][c];
            }
#pragma unroll
            for (int off = 1; off < 16; off <<= 1)
                sum += __shfl_xor_sync(0xffffffffu, sum, off);
            l_i[r] = l_i[r] * alpha + sum;
            m_i[r] = mnew;
#pragma unroll
            for (int c = 0; c < 4; c++) acc[r][c] *= alpha;
        }

        __syncthreads();   // (C) all done reading KP as K
        // Stage P row-major [q-row][j] into KP (clean float4 stores)
#pragma unroll
        for (int r = 0; r < 4; r++) {
            float4 pv;
            pv.x = s[r][0]; pv.y = s[r][1]; pv.z = s[r][2]; pv.w = s[r][3];
            *(float4*)&KP[(ty*4 + r)*64 + tx*4] = pv;
        }
        __syncthreads();   // (D)

        // O += P V  (P reads broadcast scalar; V reads contiguous float4)
#pragma unroll 16
        for (int j = 0; j < 64; j++) {
            float4 bb = *(const float4*)&Vs[j*64 + tx*4];
            float bv[4] = {bb.x, bb.y, bb.z, bb.w};
            float av[4];
#pragma unroll
            for (int r = 0; r < 4; r++) av[r] = KP[(ty*4 + r)*64 + j];
#pragma unroll
            for (int r = 0; r < 4; r++)
#pragma unroll
                for (int c = 0; c < 4; c++)
                    acc[r][c] = fmaf(av[r], bv[c], acc[r][c]);
        }
    }

    // Epilogue: normalize and write ctx [M][1024]
    float* out = ctx + (size_t)(b * SEQ + qBase) * D_MODEL + h * 64;
#pragma unroll
    for (int r = 0; r < 4; r++) {
        float inv = 1.f / l_i[r];
        float4 o;
        o.x = acc[r][0] * inv; o.y = acc[r][1] * inv;
        o.z = acc[r][2] * inv; o.w = acc[r][3] * inv;
        *(float4*)(out + (size_t)(ty*4 + r) * D_MODEL + tx*4) = o;
    }
}

// ---------------------------------------------------------------------------
extern "C" void kernel_launch(void* const* d_in, const int* in_sizes, int n_in,
                              void* d_out, int out_size)
{
    const float* x      = (const float*)d_in[0];
    const float* qkv_w  = (const float*)d_in[1];
    const float* qkv_b  = (const float*)d_in[2];
    const float* proj_w = (const float*)d_in[3];
    const float* proj_b = (const float*)d_in[4];
    float* out = (float*)d_out;

    float *qkv, *qt, *kt, *ctx;
    cudaGetSymbolAddress((void**)&qkv, g_qkv);
    cudaGetSymbolAddress((void**)&qt,  g_qt);
    cudaGetSymbolAddress((void**)&kt,  g_kt);
    cudaGetSymbolAddress((void**)&ctx, g_ctx);

    // 1) QKV projection
    sgemm_nt_bias<<<dim3(QKV_N/128, MTOT/128), 256>>>(
        x, qkv_w, qkv_b, qkv, MTOT, QKV_N, D_MODEL);

    // 2) RoPE + transpose q,k into d-major buffers
    rope_transpose<<<dim3(SEQ/64, N_HEADS, BATCH), 256>>>(qkv, qt, kt);

    // 3) Causal flash attention -> ctx
    attn_kernel<<<dim3(SEQ/64, N_HEADS, BATCH), 256>>>(qt, kt, qkv, ctx);

    // 4) Output projection
    sgemm_nt_bias<<<dim3(D_MODEL/128, MTOT/128), 256>>>(
        ctx, proj_w, proj_b, out, MTOT, D_MODEL, D_MODEL);
}